// round 1
// baseline (speedup 1.0000x reference)
#include <cuda_runtime.h>
#include <cstdint>

// SeparableConv3D: x[8,3,32,256,256] fp32, depthwise K=5 cross-correlation
// along W, then H, then T, zero 'same' padding each stage.
//
// Fused single-pass kernel:
//   lane (0..31) = t  (T == 32 == warpSize, so T-conv is done with shuffles)
//   wg   (0..7)  = group of 4 consecutive w (float4)
//   block streams over a 128-row H chunk, W-conv from a smem slab,
//   H-conv via a 5-deep register ring, T-conv via warp shuffles,
//   output transposed through smem for coalesced stores.

#define NN 8
#define CC 3
#define TT 32
#define HH 256
#define WW 256
#define KK 5

#define WT 32           // w tile (outputs) per block
#define HC 128          // h rows per block
#define XCOLS 40        // slab data cols: w0-4 .. w0+35
#define XSTRIDE 44      // 44 mod 32 = 12 -> conflict-free for lane-stride LDS.128
#define OSTRIDE 36      // 36 mod 32 = 4  -> conflict-free

__global__ void __launch_bounds__(256, 3)
sepconv3d_fused(const float* __restrict__ x,
                const float* __restrict__ w1,   // along W
                const float* __restrict__ w2,   // along H
                const float* __restrict__ w3,   // along T
                float* __restrict__ out)
{
    __shared__ float xbuf[TT * XSTRIDE];   // raw x slab for current h row, all 32 t
    __shared__ float obuf[TT * OSTRIDE];   // output transpose staging

    const int tid  = threadIdx.x;
    const int lane = tid & 31;     // = t
    const int wg   = tid >> 5;     // 0..7

    const int bid = blockIdx.x;            // 0..383
    const int nc  = bid >> 4;               // (n*3 + c), 0..23
    const int rem = bid & 15;
    const int wt  = rem >> 1;                // 0..7
    const int hcb = rem & 1;                 // 0..1
    const int c   = nc % CC;

    const int w0 = wt * WT;
    const int h0 = hcb * HC;

    // weights in registers (broadcast loads)
    float wW0 = w1[c*KK+0], wW1 = w1[c*KK+1], wW2 = w1[c*KK+2], wW3 = w1[c*KK+3], wW4 = w1[c*KK+4];
    float wH0 = w2[c*KK+0], wH1 = w2[c*KK+1], wH2 = w2[c*KK+2], wH3 = w2[c*KK+3], wH4 = w2[c*KK+4];
    float wT0 = w3[c*KK+0], wT1 = w3[c*KK+1], wT2 = w3[c*KK+2], wT3 = w3[c*KK+3], wT4 = w3[c*KK+4];

    // x base for this (n,c): element offset nc * T*H*W
    const float* xb = x + (size_t)nc * (TT * HH * WW);
    float*       ob = out + (size_t)nc * (TT * HH * WW);

    // H-conv register ring (r = W-conv result rows h_in-4 .. h_in)
    float4 g0 = {0,0,0,0}, g1 = {0,0,0,0}, g2 = {0,0,0,0}, g3 = {0,0,0,0}, g4 = {0,0,0,0};

    const int scolbase = 4 * wg;   // smem col of (w-4)

    for (int it = 0; it < HC + 4; ++it) {
        const int h_in = h0 - 2 + it;
        const bool hvalid = (h_in >= 0) && (h_in < HH);

        // -------- phase A: cooperative coalesced slab load (320 float4) --------
        {
            // item i: row tr = i/10, q = i%10, global w = w0-4+4q
            int i = tid;
            {
                int tr = i / 10, q = i - tr * 10;
                int gw = w0 - 4 + 4 * q;
                float4 v = {0,0,0,0};
                if (hvalid && gw >= 0 && gw < WW) {
                    v = *reinterpret_cast<const float4*>(
                        xb + ((size_t)tr * HH + h_in) * WW + gw);
                }
                *reinterpret_cast<float4*>(&xbuf[tr * XSTRIDE + 4 * q]) = v;
            }
            if (tid < 64) {
                i = 256 + tid;
                int tr = i / 10, q = i - tr * 10;
                int gw = w0 - 4 + 4 * q;
                float4 v = {0,0,0,0};
                if (hvalid && gw >= 0 && gw < WW) {
                    v = *reinterpret_cast<const float4*>(
                        xb + ((size_t)tr * HH + h_in) * WW + gw);
                }
                *reinterpret_cast<float4*>(&xbuf[tr * XSTRIDE + 4 * q]) = v;
            }
        }
        __syncthreads();

        // -------- phase B: W-conv (regs), H-ring, T-conv (shuffles) --------
        {
            const float* row = &xbuf[lane * XSTRIDE + scolbase];
            float4 xa = *reinterpret_cast<const float4*>(row);       // w-4..w-1
            float4 xc = *reinterpret_cast<const float4*>(row + 4);   // w  ..w+3
            float4 xe = *reinterpret_cast<const float4*>(row + 8);   // w+4..w+7

            float e0 = xa.z, e1 = xa.w, e2 = xc.x, e3 = xc.y,
                  e4 = xc.z, e5 = xc.w, e6 = xe.x, e7 = xe.y;

            float4 r;
            r.x = wW0*e0 + wW1*e1 + wW2*e2 + wW3*e3 + wW4*e4;
            r.y = wW0*e1 + wW1*e2 + wW2*e3 + wW3*e4 + wW4*e5;
            r.z = wW0*e2 + wW1*e3 + wW2*e4 + wW3*e5 + wW4*e6;
            r.w = wW0*e3 + wW1*e4 + wW2*e5 + wW3*e6 + wW4*e7;

            g0 = g1; g1 = g2; g2 = g3; g3 = g4; g4 = r;

            if (it >= 4) {
                float4 s;
                s.x = wH0*g0.x + wH1*g1.x + wH2*g2.x + wH3*g3.x + wH4*g4.x;
                s.y = wH0*g0.y + wH1*g1.y + wH2*g2.y + wH3*g3.y + wH4*g4.y;
                s.z = wH0*g0.z + wH1*g1.z + wH2*g2.z + wH3*g3.z + wH4*g4.z;
                s.w = wH0*g0.w + wH1*g1.w + wH2*g2.w + wH3*g3.w + wH4*g4.w;

                const unsigned FULL = 0xffffffffu;
                const bool u2 = (lane >= 2), u1 = (lane >= 1);
                const bool d1 = (lane <= 30), d2 = (lane <= 29);
                float4 o;
                {
                    float a2 = __shfl_up_sync(FULL, s.x, 2);
                    float a1 = __shfl_up_sync(FULL, s.x, 1);
                    float b1 = __shfl_down_sync(FULL, s.x, 1);
                    float b2 = __shfl_down_sync(FULL, s.x, 2);
                    o.x = wT2*s.x + wT0*(u2?a2:0.f) + wT1*(u1?a1:0.f)
                                  + wT3*(d1?b1:0.f) + wT4*(d2?b2:0.f);
                }
                {
                    float a2 = __shfl_up_sync(FULL, s.y, 2);
                    float a1 = __shfl_up_sync(FULL, s.y, 1);
                    float b1 = __shfl_down_sync(FULL, s.y, 1);
                    float b2 = __shfl_down_sync(FULL, s.y, 2);
                    o.y = wT2*s.y + wT0*(u2?a2:0.f) + wT1*(u1?a1:0.f)
                                  + wT3*(d1?b1:0.f) + wT4*(d2?b2:0.f);
                }
                {
                    float a2 = __shfl_up_sync(FULL, s.z, 2);
                    float a1 = __shfl_up_sync(FULL, s.z, 1);
                    float b1 = __shfl_down_sync(FULL, s.z, 1);
                    float b2 = __shfl_down_sync(FULL, s.z, 2);
                    o.z = wT2*s.z + wT0*(u2?a2:0.f) + wT1*(u1?a1:0.f)
                                  + wT3*(d1?b1:0.f) + wT4*(d2?b2:0.f);
                }
                {
                    float a2 = __shfl_up_sync(FULL, s.w, 2);
                    float a1 = __shfl_up_sync(FULL, s.w, 1);
                    float b1 = __shfl_down_sync(FULL, s.w, 1);
                    float b2 = __shfl_down_sync(FULL, s.w, 2);
                    o.w = wT2*s.w + wT0*(u2?a2:0.f) + wT1*(u1?a1:0.f)
                                  + wT3*(d1?b1:0.f) + wT4*(d2?b2:0.f);
                }
                *reinterpret_cast<float4*>(&obuf[lane * OSTRIDE + 4 * wg]) = o;
            }
        }
        __syncthreads();

        // -------- phase C: coalesced store of output row ho --------
        if (it >= 4) {
            const int ho = h0 + it - 4;
            const int t2 = tid >> 3;         // 0..31
            const int q  = tid & 7;          // 0..7
            float4 v = *reinterpret_cast<const float4*>(&obuf[t2 * OSTRIDE + 4 * q]);
            *reinterpret_cast<float4*>(
                ob + ((size_t)t2 * HH + ho) * WW + (w0 + 4 * q)) = v;
        }
        // xbuf overwrite next iter is safe: all phase-B reads happened before
        // the second barrier; obuf writes of iter i+1 happen after its first
        // barrier, which all threads reach only after finishing phase C here.
    }
}

extern "C" void kernel_launch(void* const* d_in, const int* in_sizes, int n_in,
                              void* d_out, int out_size)
{
    const float* x  = (const float*)d_in[0];
    const float* w1 = (const float*)d_in[1];
    const float* w2 = (const float*)d_in[2];
    const float* w3 = (const float*)d_in[3];
    float* out = (float*)d_out;

    // grid: 24 (n*c) * 8 (w tiles) * 2 (h chunks) = 384 blocks
    sepconv3d_fused<<<NN * CC * (WW / WT) * (HH / HC), 256>>>(x, w1, w2, w3, out);
}

// round 2
// speedup vs baseline: 1.6022x; 1.6022x over previous
#include <cuda_runtime.h>
#include <cstdint>

// SeparableConv3D: x[8,3,32,256,256] fp32, depthwise K=5 cross-correlation
// along W, then H, then T, zero 'same' padding each stage.
//
// Fused single-pass, software-pipelined:
//   lane (0..31) = t  (T == 32 == warpSize -> T-conv via shuffles)
//   wg   (0..7)  = float4 group of w
//   Double-buffered x slab + double-buffered output transpose buffer
//   => ONE __syncthreads per h-row, global loads overlapped with compute.

#define NN 8
#define CC 3
#define TT 32
#define HH 256
#define WW 256
#define KK 5

#define WT 32           // w outputs per block
#define HC 64           // h rows per block  -> grid = 24*8*4 = 768
#define XSTRIDE 44      // 44 floats/row: conflict-free LDS.128 (stride 11 chunks mod 8)
#define OSTRIDE 36

__global__ void __launch_bounds__(256, 4)
sepconv3d_fused(const float* __restrict__ x,
                const float* __restrict__ w1,   // along W
                const float* __restrict__ w2,   // along H
                const float* __restrict__ w3,   // along T
                float* __restrict__ out)
{
    __shared__ float xbuf[2][TT * XSTRIDE];
    __shared__ float obuf[2][TT * OSTRIDE];

    const int tid  = threadIdx.x;
    const int lane = tid & 31;     // = t
    const int wg   = tid >> 5;     // 0..7

    const int bid = blockIdx.x;              // 0..767
    const int nc  = bid >> 5;                 // n*3+c, 0..23
    const int rem = bid & 31;
    const int wt  = rem >> 2;                  // 0..7
    const int hcb = rem & 3;                   // 0..3
    const int c   = nc % CC;

    const int w0 = wt * WT;
    const int h0 = hcb * HC;

    const float wW0 = w1[c*KK+0], wW1 = w1[c*KK+1], wW2 = w1[c*KK+2], wW3 = w1[c*KK+3], wW4 = w1[c*KK+4];
    const float wH0 = w2[c*KK+0], wH1 = w2[c*KK+1], wH2 = w2[c*KK+2], wH3 = w2[c*KK+3], wH4 = w2[c*KK+4];
    const float wT0 = w3[c*KK+0], wT1 = w3[c*KK+1], wT2 = w3[c*KK+2], wT3 = w3[c*KK+3], wT4 = w3[c*KK+4];

    const float* xb = x   + (size_t)nc * (TT * HH * WW);
    float*       ob = out + (size_t)nc * (TT * HH * WW);

    // slab-load geometry for this thread: items tid and 256+tid (tid<64)
    const int trA = tid / 10,        qA = tid - trA * 10;
    const int iB  = 256 + tid;
    const int trB = iB / 10,         qB = iB - trB * 10;
    const int gwA = w0 - 4 + 4 * qA;
    const int gwB = w0 - 4 + 4 * qB;
    const bool wvA = (gwA >= 0) && (gwA < WW);
    const bool wvB = (tid < 64) && (gwB >= 0) && (gwB < WW);
    const size_t offA = (size_t)trA * HH * WW + gwA;
    const size_t offB = (size_t)trB * HH * WW + gwB;

    // H-conv register ring
    float4 g0 = {0,0,0,0}, g1 = {0,0,0,0}, g2 = {0,0,0,0}, g3 = {0,0,0,0}, g4 = {0,0,0,0};

    const int scolbase = 4 * wg;

    // output store geometry (phase C): thread stores (t2, quad q)
    const int t2 = tid >> 3;       // 0..31 = t
    const int qO = tid & 7;        // 0..7

    // ---- prologue: load row it=0 (h_in = h0-2) into xbuf[0] ----
    {
        const int h_in = h0 - 2;
        const bool hv = (h_in >= 0);
        float4 v = {0,0,0,0};
        if (hv && wvA) v = *reinterpret_cast<const float4*>(xb + offA + (size_t)h_in * WW);
        *reinterpret_cast<float4*>(&xbuf[0][trA * XSTRIDE + 4 * qA]) = v;
        if (tid < 64) {
            float4 u = {0,0,0,0};
            if (hv && wvB) u = *reinterpret_cast<const float4*>(xb + offB + (size_t)h_in * WW);
            *reinterpret_cast<float4*>(&xbuf[0][trB * XSTRIDE + 4 * qB]) = u;
        }
    }
    __syncthreads();

    const unsigned FULL = 0xffffffffu;
    const float mu2 = (lane >= 2) ? 1.f : 0.f;
    const float mu1 = (lane >= 1) ? 1.f : 0.f;
    const float md1 = (lane <= 30) ? 1.f : 0.f;
    const float md2 = (lane <= 29) ? 1.f : 0.f;

    #pragma unroll 1
    for (int it = 0; it < HC + 4; ++it) {
        const int cur = it & 1;

        // ---- 1. prefetch next row (h_in = h0 - 1 + it) into registers ----
        float4 p0 = {0,0,0,0}, p1 = {0,0,0,0};
        {
            const int h_in = h0 - 1 + it;
            const bool hv = (it + 1 < HC + 4) && (h_in >= 0) && (h_in < HH);
            if (hv && wvA) p0 = *reinterpret_cast<const float4*>(xb + offA + (size_t)h_in * WW);
            if (hv && wvB) p1 = *reinterpret_cast<const float4*>(xb + offB + (size_t)h_in * WW);
        }

        // ---- 2. phase B: W-conv + H-ring + T-shuffles, write obuf[cur] ----
        {
            const float* row = &xbuf[cur][lane * XSTRIDE + scolbase];
            float4 xa = *reinterpret_cast<const float4*>(row);
            float4 xc = *reinterpret_cast<const float4*>(row + 4);
            float4 xe = *reinterpret_cast<const float4*>(row + 8);

            float e0 = xa.z, e1 = xa.w, e2 = xc.x, e3 = xc.y,
                  e4 = xc.z, e5 = xc.w, e6 = xe.x, e7 = xe.y;

            float4 r;
            r.x = wW0*e0 + wW1*e1 + wW2*e2 + wW3*e3 + wW4*e4;
            r.y = wW0*e1 + wW1*e2 + wW2*e3 + wW3*e4 + wW4*e5;
            r.z = wW0*e2 + wW1*e3 + wW2*e4 + wW3*e5 + wW4*e6;
            r.w = wW0*e3 + wW1*e4 + wW2*e5 + wW3*e6 + wW4*e7;

            g0 = g1; g1 = g2; g2 = g3; g3 = g4; g4 = r;

            if (it >= 4) {
                float4 s;
                s.x = wH0*g0.x + wH1*g1.x + wH2*g2.x + wH3*g3.x + wH4*g4.x;
                s.y = wH0*g0.y + wH1*g1.y + wH2*g2.y + wH3*g3.y + wH4*g4.y;
                s.z = wH0*g0.z + wH1*g1.z + wH2*g2.z + wH3*g3.z + wH4*g4.z;
                s.w = wH0*g0.w + wH1*g1.w + wH2*g2.w + wH3*g3.w + wH4*g4.w;

                float4 o;
                {
                    float a2 = __shfl_up_sync(FULL, s.x, 2);
                    float a1 = __shfl_up_sync(FULL, s.x, 1);
                    float b1 = __shfl_down_sync(FULL, s.x, 1);
                    float b2 = __shfl_down_sync(FULL, s.x, 2);
                    o.x = wT2*s.x + wT0*mu2*a2 + wT1*mu1*a1 + wT3*md1*b1 + wT4*md2*b2;
                }
                {
                    float a2 = __shfl_up_sync(FULL, s.y, 2);
                    float a1 = __shfl_up_sync(FULL, s.y, 1);
                    float b1 = __shfl_down_sync(FULL, s.y, 1);
                    float b2 = __shfl_down_sync(FULL, s.y, 2);
                    o.y = wT2*s.y + wT0*mu2*a2 + wT1*mu1*a1 + wT3*md1*b1 + wT4*md2*b2;
                }
                {
                    float a2 = __shfl_up_sync(FULL, s.z, 2);
                    float a1 = __shfl_up_sync(FULL, s.z, 1);
                    float b1 = __shfl_down_sync(FULL, s.z, 1);
                    float b2 = __shfl_down_sync(FULL, s.z, 2);
                    o.z = wT2*s.z + wT0*mu2*a2 + wT1*mu1*a1 + wT3*md1*b1 + wT4*md2*b2;
                }
                {
                    float a2 = __shfl_up_sync(FULL, s.w, 2);
                    float a1 = __shfl_up_sync(FULL, s.w, 1);
                    float b1 = __shfl_down_sync(FULL, s.w, 1);
                    float b2 = __shfl_down_sync(FULL, s.w, 2);
                    o.w = wT2*s.w + wT0*mu2*a2 + wT1*mu1*a1 + wT3*md1*b1 + wT4*md2*b2;
                }
                *reinterpret_cast<float4*>(&obuf[cur][lane * OSTRIDE + 4 * wg]) = o;
            }
        }

        // ---- 3. phase C: store output row from PREVIOUS obuf (it-1 -> ho=h0+it-5) ----
        if (it >= 5) {
            const int ho = h0 + it - 5;
            float4 v = *reinterpret_cast<const float4*>(&obuf[cur ^ 1][t2 * OSTRIDE + 4 * qO]);
            *reinterpret_cast<float4*>(ob + ((size_t)t2 * HH + ho) * WW + (w0 + 4 * qO)) = v;
        }

        // ---- 4. commit prefetched row into xbuf[cur^1] ----
        *reinterpret_cast<float4*>(&xbuf[cur ^ 1][trA * XSTRIDE + 4 * qA]) = p0;
        if (tid < 64)
            *reinterpret_cast<float4*>(&xbuf[cur ^ 1][trB * XSTRIDE + 4 * qB]) = p1;

        __syncthreads();
        // barrier orders: xbuf[cur^1] STS vs next-iter LDS; obuf[cur] writes vs
        // next-iter phase-C reads; phase-C reads of obuf[cur^1] vs iter+1 writes.
    }

    // ---- epilogue: last output row (it = HC+3 wrote obuf[(HC+3)&1]) ----
    {
        const int ho = h0 + HC - 1;
        float4 v = *reinterpret_cast<const float4*>(&obuf[(HC + 3) & 1][t2 * OSTRIDE + 4 * qO]);
        *reinterpret_cast<float4*>(ob + ((size_t)t2 * HH + ho) * WW + (w0 + 4 * qO)) = v;
    }
}

extern "C" void kernel_launch(void* const* d_in, const int* in_sizes, int n_in,
                              void* d_out, int out_size)
{
    const float* x  = (const float*)d_in[0];
    const float* w1 = (const float*)d_in[1];
    const float* w2 = (const float*)d_in[2];
    const float* w3 = (const float*)d_in[3];
    float* out = (float*)d_out;

    // 24 (n*c) * 8 (w tiles) * 4 (h chunks) = 768 blocks
    sepconv3d_fused<<<NN * CC * (WW / WT) * (HH / HC), 256>>>(x, w1, w2, w3, out);
}

// round 3
// speedup vs baseline: 1.7474x; 1.0907x over previous
#include <cuda_runtime.h>
#include <cstdint>

// SeparableConv3D: x[8,3,32,256,256] fp32, depthwise K=5 cross-correlation
// along W, then H, then T, zero 'same' padding each stage.
//
// Fused single-pass, software-pipelined, shuffle-free:
//   phase B: W-conv (regs from x slab) + H-conv (5-deep register ring),
//            store s(t,w) into staging smem
//   phase C: T-conv = 5 LDS.128 of neighbor t-rows from the PREVIOUS
//            iteration's staging buffer (complete after last barrier),
//            coalesced STG.128
//   ONE __syncthreads per h-row; global loads prefetched one row ahead.

#define NN 8
#define CC 3
#define TT 32
#define HH 256
#define WW 256
#define KK 5

#define WT 32           // w outputs per block
#define HC 32           // h rows per block -> grid = 24*8*8 = 1536
#define XSTRIDE 44      // conflict-free for LDS.128 / STS.128 patterns used
#define OSTRIDE 36

__global__ void __launch_bounds__(256, 4)
sepconv3d_fused(const float* __restrict__ x,
                const float* __restrict__ w1,   // along W
                const float* __restrict__ w2,   // along H
                const float* __restrict__ w3,   // along T
                float* __restrict__ out)
{
    __shared__ float xbuf[2][TT * XSTRIDE];
    __shared__ float sbuf[2][TT * OSTRIDE];   // s = after W+H conv, pre T-conv

    const int tid  = threadIdx.x;
    const int lane = tid & 31;     // = t (phase B)
    const int wg   = tid >> 5;     // 0..7 (phase B float4 group)

    const int bid = blockIdx.x;               // 0..1535
    const int nc  = bid >> 6;                  // n*3+c, 0..23
    const int rem = bid & 63;
    const int wt  = rem >> 3;                   // 0..7
    const int hcb = rem & 7;                    // 0..7
    const int c   = nc % CC;

    const int w0 = wt * WT;
    const int h0 = hcb * HC;

    const float wW0 = w1[c*KK+0], wW1 = w1[c*KK+1], wW2 = w1[c*KK+2], wW3 = w1[c*KK+3], wW4 = w1[c*KK+4];
    const float wH0 = w2[c*KK+0], wH1 = w2[c*KK+1], wH2 = w2[c*KK+2], wH3 = w2[c*KK+3], wH4 = w2[c*KK+4];

    const float* xb = x   + (size_t)nc * (TT * HH * WW);
    float*       ob = out + (size_t)nc * (TT * HH * WW);

    // ---- slab-load geometry: items tid and 256+tid (tid<64) ----
    const int trA = tid / 10,  qA = tid - trA * 10;
    const int iB  = 256 + tid;
    const int trB = iB / 10,   qB = iB - trB * 10;
    const int gwA = w0 - 4 + 4 * qA;
    const int gwB = w0 - 4 + 4 * qB;
    const bool wvA = (gwA >= 0) && (gwA < WW);
    const bool wvB = (tid < 64) && (gwB >= 0) && (gwB < WW);
    const size_t offA = (size_t)trA * HH * WW + gwA;
    const size_t offB = (size_t)trB * HH * WW + gwB;

    // ---- phase C geometry: thread = (t2 output row, quad qO) ----
    const int t2 = tid >> 3;       // 0..31 = t
    const int qO = tid & 7;        // 0..7
    // T-conv: zero-masked weights + clamped smem row offsets (floats)
    const float vT0 = (t2 >= 2)  ? w3[c*KK+0] : 0.f;
    const float vT1 = (t2 >= 1)  ? w3[c*KK+1] : 0.f;
    const float vT2 =              w3[c*KK+2];
    const float vT3 = (t2 <= 30) ? w3[c*KK+3] : 0.f;
    const float vT4 = (t2 <= 29) ? w3[c*KK+4] : 0.f;
    const int cq = 4 * qO;
    const int ro0 = max(t2 - 2, 0)  * OSTRIDE + cq;
    const int ro1 = max(t2 - 1, 0)  * OSTRIDE + cq;
    const int ro2 = t2              * OSTRIDE + cq;
    const int ro3 = min(t2 + 1, 31) * OSTRIDE + cq;
    const int ro4 = min(t2 + 2, 31) * OSTRIDE + cq;

    // H-conv register ring
    float4 g0 = {0,0,0,0}, g1 = {0,0,0,0}, g2 = {0,0,0,0}, g3 = {0,0,0,0}, g4 = {0,0,0,0};

    const int scolbase = 4 * wg;

    // ---- prologue: load row it=0 (h_in = h0-2) into xbuf[0] ----
    {
        const int h_in = h0 - 2;
        const bool hv = (h_in >= 0);
        float4 v = {0,0,0,0};
        if (hv && wvA) v = *reinterpret_cast<const float4*>(xb + offA + (size_t)h_in * WW);
        *reinterpret_cast<float4*>(&xbuf[0][trA * XSTRIDE + 4 * qA]) = v;
        if (tid < 64) {
            float4 u = {0,0,0,0};
            if (hv && wvB) u = *reinterpret_cast<const float4*>(xb + offB + (size_t)h_in * WW);
            *reinterpret_cast<float4*>(&xbuf[0][trB * XSTRIDE + 4 * qB]) = u;
        }
    }
    __syncthreads();

    #pragma unroll 1
    for (int it = 0; it < HC + 4; ++it) {
        const int cur = it & 1;

        // ---- 1. prefetch next x row (h_in = h0 - 1 + it) into registers ----
        float4 p0 = {0,0,0,0}, p1 = {0,0,0,0};
        {
            const int h_in = h0 - 1 + it;
            const bool hv = (it + 1 < HC + 4) && (h_in >= 0) && (h_in < HH);
            if (hv && wvA) p0 = *reinterpret_cast<const float4*>(xb + offA + (size_t)h_in * WW);
            if (hv && wvB) p1 = *reinterpret_cast<const float4*>(xb + offB + (size_t)h_in * WW);
        }

        // ---- 2. phase B: W-conv + H-ring, write s into sbuf[cur] ----
        {
            const float* row = &xbuf[cur][lane * XSTRIDE + scolbase];
            float4 xa = *reinterpret_cast<const float4*>(row);
            float4 xc = *reinterpret_cast<const float4*>(row + 4);
            float4 xe = *reinterpret_cast<const float4*>(row + 8);

            float e0 = xa.z, e1 = xa.w, e2 = xc.x, e3 = xc.y,
                  e4 = xc.z, e5 = xc.w, e6 = xe.x, e7 = xe.y;

            float4 r;
            r.x = wW0*e0 + wW1*e1 + wW2*e2 + wW3*e3 + wW4*e4;
            r.y = wW0*e1 + wW1*e2 + wW2*e3 + wW3*e4 + wW4*e5;
            r.z = wW0*e2 + wW1*e3 + wW2*e4 + wW3*e5 + wW4*e6;
            r.w = wW0*e3 + wW1*e4 + wW2*e5 + wW3*e6 + wW4*e7;

            g0 = g1; g1 = g2; g2 = g3; g3 = g4; g4 = r;

            if (it >= 4) {
                float4 s;
                s.x = wH0*g0.x + wH1*g1.x + wH2*g2.x + wH3*g3.x + wH4*g4.x;
                s.y = wH0*g0.y + wH1*g1.y + wH2*g2.y + wH3*g3.y + wH4*g4.y;
                s.z = wH0*g0.z + wH1*g1.z + wH2*g2.z + wH3*g3.z + wH4*g4.z;
                s.w = wH0*g0.w + wH1*g1.w + wH2*g2.w + wH3*g3.w + wH4*g4.w;
                *reinterpret_cast<float4*>(&sbuf[cur][lane * OSTRIDE + 4 * wg]) = s;
            }
        }

        // ---- 3. phase C: T-conv from PREVIOUS sbuf, store row ho = h0+it-5 ----
        if (it >= 5) {
            const float* sb = sbuf[cur ^ 1];
            float4 a0 = *reinterpret_cast<const float4*>(sb + ro0);
            float4 a1 = *reinterpret_cast<const float4*>(sb + ro1);
            float4 a2 = *reinterpret_cast<const float4*>(sb + ro2);
            float4 a3 = *reinterpret_cast<const float4*>(sb + ro3);
            float4 a4 = *reinterpret_cast<const float4*>(sb + ro4);
            float4 o;
            o.x = vT0*a0.x + vT1*a1.x + vT2*a2.x + vT3*a3.x + vT4*a4.x;
            o.y = vT0*a0.y + vT1*a1.y + vT2*a2.y + vT3*a3.y + vT4*a4.y;
            o.z = vT0*a0.z + vT1*a1.z + vT2*a2.z + vT3*a3.z + vT4*a4.z;
            o.w = vT0*a0.w + vT1*a1.w + vT2*a2.w + vT3*a3.w + vT4*a4.w;
            const int ho = h0 + it - 5;
            *reinterpret_cast<float4*>(ob + ((size_t)t2 * HH + ho) * WW + (w0 + 4 * qO)) = o;
        }

        // ---- 4. commit prefetched x row into xbuf[cur^1] ----
        *reinterpret_cast<float4*>(&xbuf[cur ^ 1][trA * XSTRIDE + 4 * qA]) = p0;
        if (tid < 64)
            *reinterpret_cast<float4*>(&xbuf[cur ^ 1][trB * XSTRIDE + 4 * qB]) = p1;

        __syncthreads();
        // barrier orders: xbuf[cur^1] STS vs next-iter LDS; sbuf[cur] writes vs
        // next-iter phase-C reads; phase-C reads of sbuf[cur^1] vs iter+1 writes.
    }

    // ---- epilogue: last output row, s-row written at it = HC+3 into sbuf[(HC+3)&1] ----
    {
        const float* sb = sbuf[(HC + 3) & 1];
        float4 a0 = *reinterpret_cast<const float4*>(sb + ro0);
        float4 a1 = *reinterpret_cast<const float4*>(sb + ro1);
        float4 a2 = *reinterpret_cast<const float4*>(sb + ro2);
        float4 a3 = *reinterpret_cast<const float4*>(sb + ro3);
        float4 a4 = *reinterpret_cast<const float4*>(sb + ro4);
        float4 o;
        o.x = vT0*a0.x + vT1*a1.x + vT2*a2.x + vT3*a3.x + vT4*a4.x;
        o.y = vT0*a0.y + vT1*a1.y + vT2*a2.y + vT3*a3.y + vT4*a4.y;
        o.z = vT0*a0.z + vT1*a1.z + vT2*a2.z + vT3*a3.z + vT4*a4.z;
        o.w = vT0*a0.w + vT1*a1.w + vT2*a2.w + vT3*a3.w + vT4*a4.w;
        const int ho = h0 + HC - 1;
        *reinterpret_cast<float4*>(ob + ((size_t)t2 * HH + ho) * WW + (w0 + 4 * qO)) = o;
    }
}

extern "C" void kernel_launch(void* const* d_in, const int* in_sizes, int n_in,
                              void* d_out, int out_size)
{
    const float* x  = (const float*)d_in[0];
    const float* w1 = (const float*)d_in[1];
    const float* w2 = (const float*)d_in[2];
    const float* w3 = (const float*)d_in[3];
    float* out = (float*)d_out;

    // 24 (n*c) * 8 (w tiles) * 8 (h chunks) = 1536 blocks
    sepconv3d_fused<<<NN * CC * (WW / WT) * (HH / HC), 256>>>(x, w1, w2, w3, out);
}

// round 4
// speedup vs baseline: 1.7881x; 1.0233x over previous
#include <cuda_runtime.h>
#include <cstdint>

// SeparableConv3D: x[8,3,32,256,256] fp32, depthwise K=5 cross-correlation
// along W, then H, then T, zero 'same' padding each stage.
//
// Fused, software-pipelined, shuffle-free, t-major staging:
//   phase B (lane=t, wg=w-quad): W-conv from x slab + H-conv register ring,
//            write s(t,w) to TRANSPOSED staging sbufT[w][t] (4x STS.32)
//   phase C (lane=w, tq=t-quad): T-conv = 3 LDS.128 along t per 4 outputs,
//            4x coalesced STG.32
//   ONE __syncthreads per h-row; global loads prefetched one row ahead.

#define NN 8
#define CC 3
#define TT 32
#define HH 256
#define WW 256
#define KK 5

#define WT 32           // w outputs per block
#define HC 32           // h rows per block -> grid = 24*8*8 = 1536
#define XSTRIDE 44      // x slab row stride (conflict-free)
#define STR_T 36        // sbufT per-w stride along t (conflict-free, 16B-aligned quads)

__global__ void __launch_bounds__(256, 4)
sepconv3d_fused(const float* __restrict__ x,
                const float* __restrict__ w1,   // along W
                const float* __restrict__ w2,   // along H
                const float* __restrict__ w3,   // along T
                float* __restrict__ out)
{
    __shared__ float xbuf[2][TT * XSTRIDE];
    __shared__ float sbufT[2][WT * STR_T];   // [w][t], s = after W+H conv

    const int tid  = threadIdx.x;
    const int lane = tid & 31;     // phase B: = t
    const int wg   = tid >> 5;     // phase B: w-quad 0..7

    const int bid = blockIdx.x;               // 0..1535
    const int nc  = bid >> 6;                  // n*3+c
    const int rem = bid & 63;
    const int wt  = rem >> 3;                   // 0..7
    const int hcb = rem & 7;                    // 0..7
    const int c   = nc % CC;

    const int w0 = wt * WT;
    const int h0 = hcb * HC;

    const float wW0 = w1[c*KK+0], wW1 = w1[c*KK+1], wW2 = w1[c*KK+2], wW3 = w1[c*KK+3], wW4 = w1[c*KK+4];
    const float wH0 = w2[c*KK+0], wH1 = w2[c*KK+1], wH2 = w2[c*KK+2], wH3 = w2[c*KK+3], wH4 = w2[c*KK+4];
    const float wT0 = w3[c*KK+0], wT1 = w3[c*KK+1], wT2 = w3[c*KK+2], wT3 = w3[c*KK+3], wT4 = w3[c*KK+4];

    const float* xb = x   + (size_t)nc * (TT * HH * WW);
    float*       ob = out + (size_t)nc * (TT * HH * WW);

    // ---- slab-load geometry: items tid and 256+tid (tid<64) ----
    const int trA = tid / 10,  qA = tid - trA * 10;
    const int iB  = 256 + tid;
    const int trB = iB / 10,   qB = iB - trB * 10;
    const int gwA = w0 - 4 + 4 * qA;
    const int gwB = w0 - 4 + 4 * qB;
    const bool wvA = (gwA >= 0) && (gwA < WW);
    const bool wvB = (tid < 64) && (gwB >= 0) && (gwB < WW);
    // incremental prefetch pointers (start at h_in = h0 - 1, i.e. it=0's prefetch)
    const float* ptrA = xb + (size_t)trA * HH * WW + gwA + (size_t)(h0 - 1) * WW;
    const float* ptrB = xb + (size_t)trB * HH * WW + gwB + (size_t)(h0 - 1) * WW;

    // ---- phase C geometry: lane=w, tq = t-quad ----
    const int wl = tid & 31;       // w within tile
    const int tq = tid >> 5;       // 0..7
    const int t0 = 4 * tq;
    const int cbase = wl * STR_T;
    const int oLo  = cbase + max(t0 - 4, 0);   // quad t0-4..t0-1 (clamped)
    const int oMid = cbase + t0;               // quad t0..t0+3
    const int oHi  = cbase + min(t0 + 4, 28);  // quad t0+4..t0+7 (clamped)
    const float mlo = (tq == 0) ? 0.f : 1.f;   // zero s[-2],s[-1]
    const float mhi = (tq == 7) ? 0.f : 1.f;   // zero s[32],s[33]
    float* obase = ob + (size_t)t0 * HH * WW + w0 + wl;   // + j*HH*WW + ho*WW
    const size_t HW = (size_t)HH * WW;

    // H-conv register ring
    float4 g0 = {0,0,0,0}, g1 = {0,0,0,0}, g2 = {0,0,0,0}, g3 = {0,0,0,0}, g4 = {0,0,0,0};
    const int scolbase = 4 * wg;

    // ---- prologue: load row it=0 (h_in = h0-2) into xbuf[0] ----
    {
        const int h_in = h0 - 2;
        const bool hv = (h_in >= 0);
        float4 v = {0,0,0,0};
        if (hv && wvA) v = *reinterpret_cast<const float4*>(ptrA - WW);
        *reinterpret_cast<float4*>(&xbuf[0][trA * XSTRIDE + 4 * qA]) = v;
        if (tid < 64) {
            float4 u = {0,0,0,0};
            if (hv && wvB) u = *reinterpret_cast<const float4*>(ptrB - WW);
            *reinterpret_cast<float4*>(&xbuf[0][trB * XSTRIDE + 4 * qB]) = u;
        }
    }
    __syncthreads();

    #pragma unroll 1
    for (int it = 0; it < HC + 4; ++it) {
        const int cur = it & 1;

        // ---- 1. prefetch next x row (h_in = h0 - 1 + it) ----
        float4 p0 = {0,0,0,0}, p1 = {0,0,0,0};
        {
            const int h_in = h0 - 1 + it;
            const bool hv = (it + 1 < HC + 4) && (h_in >= 0) && (h_in < HH);
            if (hv && wvA) p0 = *reinterpret_cast<const float4*>(ptrA);
            if (hv && wvB) p1 = *reinterpret_cast<const float4*>(ptrB);
            ptrA += WW; ptrB += WW;
        }

        // ---- 2. phase B: W-conv + H-ring, transposed store into sbufT[cur] ----
        {
            const float* row = &xbuf[cur][lane * XSTRIDE + scolbase];
            float4 xa = *reinterpret_cast<const float4*>(row);
            float4 xc = *reinterpret_cast<const float4*>(row + 4);
            float4 xe = *reinterpret_cast<const float4*>(row + 8);

            float e0 = xa.z, e1 = xa.w, e2 = xc.x, e3 = xc.y,
                  e4 = xc.z, e5 = xc.w, e6 = xe.x, e7 = xe.y;

            float4 r;
            r.x = wW0*e0 + wW1*e1 + wW2*e2 + wW3*e3 + wW4*e4;
            r.y = wW0*e1 + wW1*e2 + wW2*e3 + wW3*e4 + wW4*e5;
            r.z = wW0*e2 + wW1*e3 + wW2*e4 + wW3*e5 + wW4*e6;
            r.w = wW0*e3 + wW1*e4 + wW2*e5 + wW3*e6 + wW4*e7;

            g0 = g1; g1 = g2; g2 = g3; g3 = g4; g4 = r;

            if (it >= 4) {
                float sx = wH0*g0.x + wH1*g1.x + wH2*g2.x + wH3*g3.x + wH4*g4.x;
                float sy = wH0*g0.y + wH1*g1.y + wH2*g2.y + wH3*g3.y + wH4*g4.y;
                float sz = wH0*g0.z + wH1*g1.z + wH2*g2.z + wH3*g3.z + wH4*g4.z;
                float sw = wH0*g0.w + wH1*g1.w + wH2*g2.w + wH3*g3.w + wH4*g4.w;
                float* sc = &sbufT[cur][scolbase * STR_T + lane];
                sc[0 * STR_T] = sx;
                sc[1 * STR_T] = sy;
                sc[2 * STR_T] = sz;
                sc[3 * STR_T] = sw;
            }
        }

        // ---- 3. phase C: T-conv from PREVIOUS sbufT, store row ho = h0+it-5 ----
        if (it >= 5) {
            const float* sb = sbufT[cur ^ 1];
            float4 lo  = *reinterpret_cast<const float4*>(sb + oLo);
            float4 mid = *reinterpret_cast<const float4*>(sb + oMid);
            float4 hi  = *reinterpret_cast<const float4*>(sb + oHi);
            lo.z *= mlo; lo.w *= mlo;     // zero-pad t<0
            hi.x *= mhi; hi.y *= mhi;     // zero-pad t>31

            float o0 = wT0*lo.z  + wT1*lo.w  + wT2*mid.x + wT3*mid.y + wT4*mid.z;
            float o1 = wT0*lo.w  + wT1*mid.x + wT2*mid.y + wT3*mid.z + wT4*mid.w;
            float o2 = wT0*mid.x + wT1*mid.y + wT2*mid.z + wT3*mid.w + wT4*hi.x;
            float o3 = wT0*mid.y + wT1*mid.z + wT2*mid.w + wT3*hi.x  + wT4*hi.y;

            float* op = obase + (size_t)(h0 + it - 5) * WW;
            op[0]      = o0;
            op[HW]     = o1;
            op[2 * HW] = o2;
            op[3 * HW] = o3;
        }

        // ---- 4. commit prefetched x row into xbuf[cur^1] ----
        *reinterpret_cast<float4*>(&xbuf[cur ^ 1][trA * XSTRIDE + 4 * qA]) = p0;
        if (tid < 64)
            *reinterpret_cast<float4*>(&xbuf[cur ^ 1][trB * XSTRIDE + 4 * qB]) = p1;

        __syncthreads();
    }

    // ---- epilogue: last output row from sbufT[(HC+3)&1], ho = h0+HC-1 ----
    {
        const float* sb = sbufT[(HC + 3) & 1];
        float4 lo  = *reinterpret_cast<const float4*>(sb + oLo);
        float4 mid = *reinterpret_cast<const float4*>(sb + oMid);
        float4 hi  = *reinterpret_cast<const float4*>(sb + oHi);
        lo.z *= mlo; lo.w *= mlo;
        hi.x *= mhi; hi.y *= mhi;

        float o0 = wT0*lo.z  + wT1*lo.w  + wT2*mid.x + wT3*mid.y + wT4*mid.z;
        float o1 = wT0*lo.w  + wT1*mid.x + wT2*mid.y + wT3*mid.z + wT4*mid.w;
        float o2 = wT0*mid.x + wT1*mid.y + wT2*mid.z + wT3*mid.w + wT4*hi.x;
        float o3 = wT0*mid.y + wT1*mid.z + wT2*mid.w + wT3*hi.x  + wT4*hi.y;

        float* op = obase + (size_t)(h0 + HC - 1) * WW;
        op[0]      = o0;
        op[HW]     = o1;
        op[2 * HW] = o2;
        op[3 * HW] = o3;
    }
}

extern "C" void kernel_launch(void* const* d_in, const int* in_sizes, int n_in,
                              void* d_out, int out_size)
{
    const float* x  = (const float*)d_in[0];
    const float* w1 = (const float*)d_in[1];
    const float* w2 = (const float*)d_in[2];
    const float* w3 = (const float*)d_in[3];
    float* out = (float*)d_out;

    // 24 (n*c) * 8 (w tiles) * 8 (h chunks) = 1536 blocks
    sepconv3d_fused<<<NN * CC * (WW / WT) * (HH / HC), 256>>>(x, w1, w2, w3, out);
}